// round 2
// baseline (speedup 1.0000x reference)
#include <cuda_runtime.h>
#include <math.h>

// Problem constants (fixed by the dataset)
#define NN    10000          // nodes
#define EE    320000         // edges (before self loops)
#define ET    (EE + NN)      // edges incl. self loops
#define HH    4              // heads
#define CC    128            // channels per head
#define HC    (HH * CC)      // 512

// ---------------- scratch (static device globals; no allocs allowed) ----------
__device__ float g_h[NN * HC];          // projected features [N, H*C]  (20.5 MB)
__device__ float g_asrc[NN * HH];       // per-node src attention logits
__device__ float g_adst[NN * HH];       // per-node dst attention logits
__device__ int   g_count[NN];           // in-degree counts
__device__ int   g_off[NN + 1];         // CSR offsets
__device__ int   g_cursor[NN];          // fill cursors
__device__ int   g_src[ET];             // edge sources sorted by destination
__device__ int   g_is64;                // 1 if edge buffer is int64, 0 if int32

// ---------------- init: zero counters (must happen every replay) --------------
__global__ void init_kernel() {
    int i = blockIdx.x * blockDim.x + threadIdx.x;
    if (i < NN) { g_count[i] = 0; g_cursor[i] = 0; }
}

// ---------------- detect edge dtype -------------------------------------------
// int64 little-endian with values < 2^31 => every odd int32 word is 0.
// Sample 1024 odd positions (all within the first 8KB, in bounds for either
// dtype since the buffer is >= 2.56 MB).
__global__ void detect_kernel(const int* __restrict__ e32) {
    __shared__ int bad;
    if (threadIdx.x == 0) bad = 0;
    __syncthreads();
    for (int k = threadIdx.x; k < 1024; k += blockDim.x) {
        if (e32[2 * k + 1] != 0) atomicOr(&bad, 1);
    }
    __syncthreads();
    if (threadIdx.x == 0) g_is64 = bad ? 0 : 1;
}

// ---------------- GEMM: h[N, 512] = x[N,128] @ W[128,512] ---------------------
// 64x64 tile, 256 threads, 4x4 micro-tile, K-steps of 16.
__global__ void gemm_kernel(const float* __restrict__ x, const float* __restrict__ W) {
    __shared__ float xs[16][64 + 1];
    __shared__ float ws[16][64];
    const int tx = threadIdx.x & 15;       // 0..15 -> cols
    const int ty = threadIdx.x >> 4;       // 0..15 -> rows
    const int row0 = blockIdx.x * 64;
    const int col0 = blockIdx.y * 64;
    float acc[4][4];
#pragma unroll
    for (int i = 0; i < 4; i++)
#pragma unroll
        for (int j = 0; j < 4; j++) acc[i][j] = 0.f;

    for (int kk = 0; kk < CC; kk += 16) {
        for (int t = threadIdx.x; t < 64 * 16; t += 256) {
            int m = t >> 4, k = t & 15;
            int gr = row0 + m;
            xs[k][m] = (gr < NN) ? x[gr * CC + kk + k] : 0.f;
        }
        for (int t = threadIdx.x; t < 16 * 64; t += 256) {
            int k = t >> 6, c = t & 63;
            ws[k][c] = W[(kk + k) * HC + col0 + c];
        }
        __syncthreads();
#pragma unroll
        for (int k = 0; k < 16; k++) {
            float a[4], b[4];
#pragma unroll
            for (int i = 0; i < 4; i++) a[i] = xs[k][ty * 4 + i];
#pragma unroll
            for (int j = 0; j < 4; j++) b[j] = ws[k][tx * 4 + j];
#pragma unroll
            for (int i = 0; i < 4; i++)
#pragma unroll
                for (int j = 0; j < 4; j++) acc[i][j] += a[i] * b[j];
        }
        __syncthreads();
    }
#pragma unroll
    for (int i = 0; i < 4; i++) {
        int gr = row0 + ty * 4 + i;
        if (gr < NN) {
#pragma unroll
            for (int j = 0; j < 4; j++)
                g_h[gr * HC + col0 + tx * 4 + j] = acc[i][j];
        }
    }
}

// ---------------- attention dots: a_src[n,h], a_dst[n,h] ----------------------
// one warp per (node, head); dot of 128 elements
__global__ void attndot_kernel(const float* __restrict__ att_src,
                               const float* __restrict__ att_dst) {
    int w = blockIdx.x * (blockDim.x >> 5) + (threadIdx.x >> 5);
    if (w >= NN * HH) return;
    int lane = threadIdx.x & 31;
    int n = w >> 2;
    int hh = w & 3;
    const float4* hv = (const float4*)&g_h[n * HC + hh * CC];
    const float4* sv = (const float4*)&att_src[hh * CC];
    const float4* dv = (const float4*)&att_dst[hh * CC];
    float4 a = hv[lane];
    float4 s = sv[lane];
    float4 d = dv[lane];
    float vs = a.x * s.x + a.y * s.y + a.z * s.z + a.w * s.w;
    float vd = a.x * d.x + a.y * d.y + a.z * d.z + a.w * d.w;
#pragma unroll
    for (int off = 16; off > 0; off >>= 1) {
        vs += __shfl_down_sync(0xFFFFFFFFu, vs, off);
        vd += __shfl_down_sync(0xFFFFFFFFu, vd, off);
    }
    if (lane == 0) {
        g_asrc[n * HH + hh] = vs;
        g_adst[n * HH + hh] = vd;
    }
}

// ---------------- edge fetch helpers ------------------------------------------
__device__ __forceinline__ int edge_at(const void* edge, long long idx, int is64) {
    if (is64) return (int)((const long long*)edge)[idx];
    return ((const int*)edge)[idx];
}

// ---------------- count in-degrees (edges + self loops) -----------------------
__global__ void count_kernel(const void* __restrict__ edge) {
    int e = blockIdx.x * blockDim.x + threadIdx.x;
    if (e >= ET) return;
    int is64 = g_is64;
    int d = (e < EE) ? edge_at(edge, (long long)EE + e, is64) : (e - EE);
    if ((unsigned)d < NN) atomicAdd(&g_count[d], 1);
}

// ---------------- exclusive scan of counts -> offsets (single block) ----------
__global__ void scan_kernel() {
    const int CH = 10;  // 1024 * 10 >= 10000
    int tid = threadIdx.x;
    int base = tid * CH;
    int vals[CH];
    int tsum = 0;
#pragma unroll
    for (int c = 0; c < CH; c++) {
        int idx = base + c;
        int v = (idx < NN) ? g_count[idx] : 0;
        vals[c] = v;
        tsum += v;
    }
    int lane = tid & 31, wid = tid >> 5;
    int inc = tsum;
#pragma unroll
    for (int off = 1; off < 32; off <<= 1) {
        int y = __shfl_up_sync(0xFFFFFFFFu, inc, off);
        if (lane >= off) inc += y;
    }
    __shared__ int wsum[32];
    if (lane == 31) wsum[wid] = inc;
    __syncthreads();
    if (wid == 0) {
        int w = wsum[lane];
        int wi = w;
#pragma unroll
        for (int off = 1; off < 32; off <<= 1) {
            int y = __shfl_up_sync(0xFFFFFFFFu, wi, off);
            if (lane >= off) wi += y;
        }
        wsum[lane] = wi - w;  // exclusive warp offsets
    }
    __syncthreads();
    int ex = (inc - tsum) + wsum[wid];
    int run = ex;
#pragma unroll
    for (int c = 0; c < CH; c++) {
        int idx = base + c;
        if (idx < NN) g_off[idx] = run;
        run += vals[c];
    }
    if (tid == 1023) g_off[NN] = run;
}

// ---------------- scatter edges into CSR (sorted by destination) --------------
__global__ void fill_kernel(const void* __restrict__ edge) {
    int e = blockIdx.x * blockDim.x + threadIdx.x;
    if (e >= ET) return;
    int is64 = g_is64;
    int s, d;
    if (e < EE) {
        s = edge_at(edge, (long long)e, is64);
        d = edge_at(edge, (long long)EE + e, is64);
    } else {
        s = e - EE; d = e - EE;
    }
    if ((unsigned)d >= NN || (unsigned)s >= NN) return;  // must mirror count_kernel
    int pos = g_off[d] + atomicAdd(&g_cursor[d], 1);
    if ((unsigned)pos < ET) g_src[pos] = s;
}

// ---------------- softmax + weighted aggregation ------------------------------
// one 128-thread block per (node, head); thread t owns channel t
__global__ void agg_kernel(const float* __restrict__ bias, float* __restrict__ out) {
    const int i   = blockIdx.x;   // destination node
    const int hh  = blockIdx.y;   // head
    const int tid = threadIdx.x;  // channel
    const int beg = g_off[i];
    const int end = g_off[i + 1];
    const float adst = g_adst[i * HH + hh];

    __shared__ float red[128];

    // pass 1: max logit
    float m = -INFINITY;
    for (int j = beg + tid; j < end; j += 128) {
        int s = g_src[j];
        float l = g_asrc[s * HH + hh] + adst;
        l = (l > 0.f) ? l : 0.2f * l;
        m = fmaxf(m, l);
    }
    red[tid] = m;
    __syncthreads();
#pragma unroll
    for (int s2 = 64; s2 > 0; s2 >>= 1) {
        if (tid < s2) red[tid] = fmaxf(red[tid], red[tid + s2]);
        __syncthreads();
    }
    m = red[0];
    __syncthreads();

    // pass 2: sum of exp
    float ssum = 0.f;
    for (int j = beg + tid; j < end; j += 128) {
        int s = g_src[j];
        float l = g_asrc[s * HH + hh] + adst;
        l = (l > 0.f) ? l : 0.2f * l;
        ssum += __expf(l - m);
    }
    red[tid] = ssum;
    __syncthreads();
#pragma unroll
    for (int s2 = 64; s2 > 0; s2 >>= 1) {
        if (tid < s2) red[tid] += red[tid + s2];
        __syncthreads();
    }
    const float inv = 1.f / (red[0] + 1e-16f);
    __syncthreads();

    // pass 3: chunked alpha + coalesced gather-accumulate
    __shared__ float sa[128];
    __shared__ int   ss[128];
    float acc = 0.f;
    for (int chunk = beg; chunk < end; chunk += 128) {
        int j = chunk + tid;
        if (j < end) {
            int s = g_src[j];
            float l = g_asrc[s * HH + hh] + adst;
            l = (l > 0.f) ? l : 0.2f * l;
            sa[tid] = __expf(l - m) * inv;
            ss[tid] = s;
        }
        __syncthreads();
        int cl = min(128, end - chunk);
        for (int k = 0; k < cl; k++) {
            acc += sa[k] * g_h[ss[k] * HC + hh * CC + tid];
        }
        __syncthreads();
    }
    out[i * HC + hh * CC + tid] = acc + bias[hh * CC + tid];
}

// ---------------- launch -------------------------------------------------------
extern "C" void kernel_launch(void* const* d_in, const int* in_sizes, int n_in,
                              void* d_out, int out_size) {
    const float* x       = (const float*)d_in[0];
    const float* W       = (const float*)d_in[1];
    const float* att_src = (const float*)d_in[2];
    const float* att_dst = (const float*)d_in[3];
    const float* bias    = (const float*)d_in[4];
    const void*  edge    = d_in[5];
    float*       out     = (float*)d_out;

    init_kernel<<<(NN + 255) / 256, 256>>>();
    detect_kernel<<<1, 256>>>((const int*)edge);
    gemm_kernel<<<dim3((NN + 63) / 64, HC / 64), 256>>>(x, W);
    attndot_kernel<<<(NN * HH + 7) / 8, 256>>>(att_src, att_dst);
    count_kernel<<<(ET + 255) / 256, 256>>>(edge);
    scan_kernel<<<1, 1024>>>();
    fill_kernel<<<(ET + 255) / 256, 256>>>(edge);
    agg_kernel<<<dim3(NN, HH), 128>>>(bias, out);
}

// round 4
// speedup vs baseline: 1.4622x; 1.4622x over previous
#include <cuda_runtime.h>
#include <math.h>

// Problem constants (fixed by the dataset)
#define NN    10000          // nodes
#define EE    320000         // edges (before self loops)
#define ET    (EE + NN)      // edges incl. self loops
#define HH    4              // heads
#define CC    128            // channels per head
#define HC    (HH * CC)      // 512
#define CAP   512            // agg chunk size (edges per shared-mem chunk)

// ---------------- scratch (static device globals; no allocs allowed) ----------
__device__ float g_h[NN * HC];          // projected features [N, H*C]  (20.5 MB)
__device__ float g_asrc[NN * HH];       // per-node src attention logits [N,4]
__device__ float g_adst[NN * HH];       // per-node dst attention logits [N,4]
__device__ int   g_count[NN];           // in-degree counts
__device__ int   g_off[NN + 1];         // CSR offsets
__device__ int   g_cursor[NN];          // fill cursors
__device__ int   g_src[ET];             // edge sources sorted by destination
__device__ int   g_is64;                // 1 if edge buffer is int64, 0 if int32

// ---------------- init: zero counters (must happen every replay) --------------
__global__ void init_kernel() {
    int i = blockIdx.x * blockDim.x + threadIdx.x;
    if (i < NN) { g_count[i] = 0; g_cursor[i] = 0; }
}

// ---------------- detect edge dtype -------------------------------------------
// int64 little-endian with values < 2^31 => every odd int32 word is 0.
__global__ void detect_kernel(const int* __restrict__ e32) {
    __shared__ int bad;
    if (threadIdx.x == 0) bad = 0;
    __syncthreads();
    for (int k = threadIdx.x; k < 1024; k += blockDim.x) {
        if (e32[2 * k + 1] != 0) atomicOr(&bad, 1);
    }
    __syncthreads();
    if (threadIdx.x == 0) g_is64 = bad ? 0 : 1;
}

// ---------------- GEMM + fused attention dots ---------------------------------
// h[N,512] = x[N,128] @ W[128,512].  128x128 tile, 256 threads, 8x8 microtile.
// Each block's 128 cols == one full head, so a_src/a_dst dots complete here.
__global__ void __launch_bounds__(256) gemm_kernel(
        const float* __restrict__ x, const float* __restrict__ W,
        const float* __restrict__ att_src, const float* __restrict__ att_dst) {
    __shared__ float xs[16][128];   // x^T tile: xs[k][m]
    __shared__ float ws[16][128];   // W tile:  ws[k][c]
    const int tx = threadIdx.x & 15;
    const int ty = threadIdx.x >> 4;
    const int row0 = blockIdx.x * 128;
    const int head = blockIdx.y;          // col0 = head*128
    const int col0 = head * CC;

    float acc[8][8];
#pragma unroll
    for (int i = 0; i < 8; i++)
#pragma unroll
        for (int j = 0; j < 8; j++) acc[i][j] = 0.f;

    for (int kk = 0; kk < CC; kk += 16) {
        // load x tile: 128 rows x 16 k. Each thread: 2 float4 (8 floats).
        {
            int m = threadIdx.x >> 1;
            int gr = row0 + m;
#pragma unroll
            for (int q = 0; q < 2; q++) {
                int k4 = (threadIdx.x & 1) * 2 + q;       // float4 index 0..3
                float4 v = make_float4(0.f, 0.f, 0.f, 0.f);
                if (gr < NN) v = *(const float4*)&x[gr * CC + kk + k4 * 4];
                xs[k4 * 4 + 0][m] = v.x;
                xs[k4 * 4 + 1][m] = v.y;
                xs[k4 * 4 + 2][m] = v.z;
                xs[k4 * 4 + 3][m] = v.w;
            }
        }
        // load W tile: 16 k x 128 cols. Each thread: 2 float4.
        {
#pragma unroll
            for (int q = 0; q < 2; q++) {
                int t = threadIdx.x + q * 256;           // 0..511 float4 slots
                int k = t >> 5;                          // 32 float4 per row
                int c4 = t & 31;
                float4 v = *(const float4*)&W[(kk + k) * HC + col0 + c4 * 4];
                *(float4*)&ws[k][c4 * 4] = v;
            }
        }
        __syncthreads();
#pragma unroll
        for (int k = 0; k < 16; k++) {
            float a[8], b[8];
#pragma unroll
            for (int i = 0; i < 8; i++) a[i] = xs[k][ty * 8 + i];
#pragma unroll
            for (int j = 0; j < 8; j++) b[j] = ws[k][tx * 8 + j];
#pragma unroll
            for (int i = 0; i < 8; i++)
#pragma unroll
                for (int j = 0; j < 8; j++) acc[i][j] += a[i] * b[j];
        }
        __syncthreads();
    }

    // store h
#pragma unroll
    for (int i = 0; i < 8; i++) {
        int gr = row0 + ty * 8 + i;
        if (gr < NN) {
#pragma unroll
            for (int j = 0; j < 8; j += 4) {
                float4 v = make_float4(acc[i][j], acc[i][j+1], acc[i][j+2], acc[i][j+3]);
                *(float4*)&g_h[(size_t)gr * HC + col0 + tx * 8 + j] = v;
            }
        }
    }

    // fused attention dots: vs_i = sum_j acc[i][j]*att_src[head, tx*8+j]
    float as[8], ad[8];
#pragma unroll
    for (int j = 0; j < 8; j++) {
        as[j] = att_src[head * CC + tx * 8 + j];
        ad[j] = att_dst[head * CC + tx * 8 + j];
    }
#pragma unroll
    for (int i = 0; i < 8; i++) {
        float vs = 0.f, vd = 0.f;
#pragma unroll
        for (int j = 0; j < 8; j++) { vs += acc[i][j] * as[j]; vd += acc[i][j] * ad[j]; }
        // reduce across the 16 tx lanes (contiguous lanes within half-warp)
#pragma unroll
        for (int off = 8; off > 0; off >>= 1) {
            vs += __shfl_down_sync(0xFFFFFFFFu, vs, off, 16);
            vd += __shfl_down_sync(0xFFFFFFFFu, vd, off, 16);
        }
        int gr = row0 + ty * 8 + i;
        if (tx == 0 && gr < NN) {
            g_asrc[gr * HH + head] = vs;
            g_adst[gr * HH + head] = vd;
        }
    }
}

// ---------------- edge fetch helper -------------------------------------------
__device__ __forceinline__ int edge_at(const void* edge, long long idx, int is64) {
    if (is64) return (int)((const long long*)edge)[idx];
    return ((const int*)edge)[idx];
}

// ---------------- count in-degrees (edges + self loops) -----------------------
__global__ void count_kernel(const void* __restrict__ edge) {
    int e = blockIdx.x * blockDim.x + threadIdx.x;
    if (e >= ET) return;
    int is64 = g_is64;
    int d = (e < EE) ? edge_at(edge, (long long)EE + e, is64) : (e - EE);
    if ((unsigned)d < NN) atomicAdd(&g_count[d], 1);
}

// ---------------- exclusive scan of counts -> offsets (single block) ----------
__global__ void scan_kernel() {
    const int CH = 10;
    int tid = threadIdx.x;
    int base = tid * CH;
    int vals[CH];
    int tsum = 0;
#pragma unroll
    for (int c = 0; c < CH; c++) {
        int idx = base + c;
        int v = (idx < NN) ? g_count[idx] : 0;
        vals[c] = v;
        tsum += v;
    }
    int lane = tid & 31, wid = tid >> 5;
    int inc = tsum;
#pragma unroll
    for (int off = 1; off < 32; off <<= 1) {
        int y = __shfl_up_sync(0xFFFFFFFFu, inc, off);
        if (lane >= off) inc += y;
    }
    __shared__ int wsum[32];
    if (lane == 31) wsum[wid] = inc;
    __syncthreads();
    if (wid == 0) {
        int w = wsum[lane];
        int wi = w;
#pragma unroll
        for (int off = 1; off < 32; off <<= 1) {
            int y = __shfl_up_sync(0xFFFFFFFFu, wi, off);
            if (lane >= off) wi += y;
        }
        wsum[lane] = wi - w;
    }
    __syncthreads();
    int ex = (inc - tsum) + wsum[wid];
    int run = ex;
#pragma unroll
    for (int c = 0; c < CH; c++) {
        int idx = base + c;
        if (idx < NN) g_off[idx] = run;
        run += vals[c];
    }
    if (tid == 1023) g_off[NN] = run;
}

// ---------------- scatter edges into CSR (sorted by destination) --------------
__global__ void fill_kernel(const void* __restrict__ edge) {
    int e = blockIdx.x * blockDim.x + threadIdx.x;
    if (e >= ET) return;
    int is64 = g_is64;
    int s, d;
    if (e < EE) {
        s = edge_at(edge, (long long)e, is64);
        d = edge_at(edge, (long long)EE + e, is64);
    } else {
        s = e - EE; d = e - EE;
    }
    if ((unsigned)d >= NN || (unsigned)s >= NN) return;
    int pos = g_off[d] + atomicAdd(&g_cursor[d], 1);
    if ((unsigned)pos < ET) g_src[pos] = s;
}

// ---------------- softmax + weighted aggregation (all heads in one block) -----
// 128 threads per node. Thread t owns float4 channels [t*4, t*4+4) of the
// 512-wide output row; its head is t>>5. Warp w does head-w softmax reductions.
// Online-softmax chunking handles arbitrary degree (1 chunk when deg <= CAP).
__global__ void __launch_bounds__(128) agg_kernel(
        const float* __restrict__ bias, float* __restrict__ out) {
    const int i    = blockIdx.x;
    const int tid  = threadIdx.x;        // 0..127
    const int head = tid >> 5;           // warp id == head
    const int lane = tid & 31;
    const int beg  = g_off[i];
    const int deg  = g_off[i + 1] - beg;

    __shared__ float s_e[HH * CAP];      // per-head unnormalized exp weights
    __shared__ int   s_src[CAP];

    const float4 adst = *(const float4*)&g_adst[i * HH];

    float m_run = -INFINITY;
    float s_run = 0.f;
    float4 acc = make_float4(0.f, 0.f, 0.f, 0.f);

    for (int c0 = 0; c0 < deg; c0 += CAP) {
        const int cl = min(CAP, deg - c0);

        // load chunk: sources + 4 head logits per edge
        for (int j = tid; j < cl; j += 128) {
            int s = g_src[beg + c0 + j];
            s_src[j] = s;
            float4 a = *(const float4*)&g_asrc[s * HH];
            float l0 = a.x + adst.x; l0 = (l0 > 0.f) ? l0 : 0.2f * l0;
            float l1 = a.y + adst.y; l1 = (l1 > 0.f) ? l1 : 0.2f * l1;
            float l2 = a.z + adst.z; l2 = (l2 > 0.f) ? l2 : 0.2f * l2;
            float l3 = a.w + adst.w; l3 = (l3 > 0.f) ? l3 : 0.2f * l3;
            s_e[0 * CAP + j] = l0;
            s_e[1 * CAP + j] = l1;
            s_e[2 * CAP + j] = l2;
            s_e[3 * CAP + j] = l3;
        }
        __syncthreads();

        // per-head (per-warp) chunk max
        float m_new = -INFINITY;
        for (int j = lane; j < cl; j += 32)
            m_new = fmaxf(m_new, s_e[head * CAP + j]);
#pragma unroll
        for (int off = 16; off > 0; off >>= 1)
            m_new = fmaxf(m_new, __shfl_xor_sync(0xFFFFFFFFu, m_new, off));

        float m2 = fmaxf(m_run, m_new);
        float scale = __expf(m_run - m2);   // exp(-inf)=0 handles first chunk

        // exponentiate in place + chunk sum
        float csum = 0.f;
        for (int j = lane; j < cl; j += 32) {
            float e = __expf(s_e[head * CAP + j] - m2);
            s_e[head * CAP + j] = e;
            csum += e;
        }
#pragma unroll
        for (int off = 16; off > 0; off >>= 1)
            csum += __shfl_xor_sync(0xFFFFFFFFu, csum, off);

        s_run = s_run * scale + csum;
        m_run = m2;
        acc.x *= scale; acc.y *= scale; acc.z *= scale; acc.w *= scale;
        __syncthreads();

        // gather: per edge one coalesced float4 per thread (full 512-f row)
#pragma unroll 4
        for (int k = 0; k < cl; k++) {
            int s = s_src[k];                      // smem broadcast
            float al = s_e[head * CAP + k];        // smem broadcast per warp
            float4 v = *(const float4*)&g_h[(size_t)s * HC + tid * 4];
            acc.x += al * v.x;
            acc.y += al * v.y;
            acc.z += al * v.z;
            acc.w += al * v.w;
        }
        __syncthreads();
    }

    const float inv = 1.f / (s_run + 1e-16f);
    const float4 b = *(const float4*)&bias[tid * 4];
    float4 o;
    o.x = acc.x * inv + b.x;
    o.y = acc.y * inv + b.y;
    o.z = acc.z * inv + b.z;
    o.w = acc.w * inv + b.w;
    *(float4*)&out[(size_t)i * HC + tid * 4] = o;
}

// ---------------- launch -------------------------------------------------------
extern "C" void kernel_launch(void* const* d_in, const int* in_sizes, int n_in,
                              void* d_out, int out_size) {
    const float* x       = (const float*)d_in[0];
    const float* W       = (const float*)d_in[1];
    const float* att_src = (const float*)d_in[2];
    const float* att_dst = (const float*)d_in[3];
    const float* bias    = (const float*)d_in[4];
    const void*  edge    = d_in[5];
    float*       out     = (float*)d_out;

    init_kernel<<<(NN + 255) / 256, 256>>>();
    detect_kernel<<<1, 256>>>((const int*)edge);
    gemm_kernel<<<dim3((NN + 127) / 128, HH), 256>>>(x, W, att_src, att_dst);
    count_kernel<<<(ET + 255) / 256, 256>>>(edge);
    scan_kernel<<<1, 1024>>>();
    fill_kernel<<<(ET + 255) / 256, 256>>>(edge);
    agg_kernel<<<NN, 128>>>(bias, out);
}

// round 6
// speedup vs baseline: 1.6165x; 1.1055x over previous
#include <cuda_runtime.h>
#include <cuda_fp16.h>
#include <math.h>

// Problem constants (fixed by the dataset)
#define NN    10000          // nodes
#define EE    320000         // edges (before self loops)
#define ET    (EE + NN)      // edges incl. self loops
#define HH    4              // heads
#define CC    128            // channels per head
#define HC    (HH * CC)      // 512
#define CAP   512            // agg chunk size (edges per shared-mem chunk)
#define EB    4              // edges per thread in count/fill

// ---------------- scratch (static device globals; no allocs allowed) ----------
__device__ __half2 g_h2[NN * HC / 2];   // projected features, fp16 [N, H*C] (10.2 MB)
__device__ float g_asrc[NN * HH];       // per-node src attention logits [N,4]
__device__ float g_adst[NN * HH];       // per-node dst attention logits [N,4]
__device__ int   g_count[NN];           // in-degree counts
__device__ int   g_off[NN + 1];         // CSR offsets
__device__ int   g_cursor[NN];          // fill cursors
__device__ int   g_src[ET];             // edge sources sorted by destination
__device__ int   g_is64;                // 1 if edge buffer is int64, 0 if int32

// ---------------- setup: zero counters + detect edge dtype --------------------
// int64 little-endian with values < 2^31 => every odd int32 word is 0.
__global__ void setup_kernel(const int* __restrict__ e32) {
    int i = blockIdx.x * blockDim.x + threadIdx.x;
    if (i < NN) { g_count[i] = 0; g_cursor[i] = 0; }
    if (blockIdx.x == 0) {
        __shared__ int bad;
        if (threadIdx.x == 0) bad = 0;
        __syncthreads();
        int any = 0;
        for (int k = threadIdx.x; k < 1024; k += blockDim.x)
            any |= (e32[2 * k + 1] != 0);
        if (any) atomicOr(&bad, 1);
        __syncthreads();
        if (threadIdx.x == 0) g_is64 = bad ? 0 : 1;
    }
}

// ---------------- GEMM + fused attention dots ---------------------------------
// h[N,512] = x[N,128] @ W[128,512].  128x128 tile, 256 threads, 8x8 microtile.
// Each block's 128 cols == one full head; h stored as fp16.
__global__ void __launch_bounds__(256) gemm_kernel(
        const float* __restrict__ x, const float* __restrict__ W,
        const float* __restrict__ att_src, const float* __restrict__ att_dst) {
    __shared__ float xs[16][128];
    __shared__ float ws[16][128];
    const int tx = threadIdx.x & 15;
    const int ty = threadIdx.x >> 4;
    const int row0 = blockIdx.x * 128;
    const int head = blockIdx.y;
    const int col0 = head * CC;

    float acc[8][8];
#pragma unroll
    for (int i = 0; i < 8; i++)
#pragma unroll
        for (int j = 0; j < 8; j++) acc[i][j] = 0.f;

    for (int kk = 0; kk < CC; kk += 16) {
        {
            int m = threadIdx.x >> 1;
            int gr = row0 + m;
#pragma unroll
            for (int q = 0; q < 2; q++) {
                int k4 = (threadIdx.x & 1) * 2 + q;
                float4 v = make_float4(0.f, 0.f, 0.f, 0.f);
                if (gr < NN) v = *(const float4*)&x[gr * CC + kk + k4 * 4];
                xs[k4 * 4 + 0][m] = v.x;
                xs[k4 * 4 + 1][m] = v.y;
                xs[k4 * 4 + 2][m] = v.z;
                xs[k4 * 4 + 3][m] = v.w;
            }
        }
        {
#pragma unroll
            for (int q = 0; q < 2; q++) {
                int t = threadIdx.x + q * 256;
                int k = t >> 5;
                int c4 = t & 31;
                float4 v = *(const float4*)&W[(kk + k) * HC + col0 + c4 * 4];
                *(float4*)&ws[k][c4 * 4] = v;
            }
        }
        __syncthreads();
#pragma unroll
        for (int k = 0; k < 16; k++) {
            float a[8], b[8];
#pragma unroll
            for (int i = 0; i < 8; i++) a[i] = xs[k][ty * 8 + i];
#pragma unroll
            for (int j = 0; j < 8; j++) b[j] = ws[k][tx * 8 + j];
#pragma unroll
            for (int i = 0; i < 8; i++)
#pragma unroll
                for (int j = 0; j < 8; j++) acc[i][j] += a[i] * b[j];
        }
        __syncthreads();
    }

    // store h as fp16 (8 floats -> 4 half2 -> one 16B write)
#pragma unroll
    for (int i = 0; i < 8; i++) {
        int gr = row0 + ty * 8 + i;
        if (gr < NN) {
            union alignas(16) { __half2 h2[4]; float4 f4; } u;
#pragma unroll
            for (int j = 0; j < 4; j++)
                u.h2[j] = __floats2half2_rn(acc[i][2 * j], acc[i][2 * j + 1]);
            *(float4*)&g_h2[(size_t)gr * (HC / 2) + (col0 + tx * 8) / 2] = u.f4;
        }
    }

    // fused attention dots (fp32 accumulators)
    float as[8], ad[8];
#pragma unroll
    for (int j = 0; j < 8; j++) {
        as[j] = att_src[head * CC + tx * 8 + j];
        ad[j] = att_dst[head * CC + tx * 8 + j];
    }
#pragma unroll
    for (int i = 0; i < 8; i++) {
        float vs = 0.f, vd = 0.f;
#pragma unroll
        for (int j = 0; j < 8; j++) { vs += acc[i][j] * as[j]; vd += acc[i][j] * ad[j]; }
#pragma unroll
        for (int off = 8; off > 0; off >>= 1) {
            vs += __shfl_down_sync(0xFFFFFFFFu, vs, off, 16);
            vd += __shfl_down_sync(0xFFFFFFFFu, vd, off, 16);
        }
        int gr = row0 + ty * 8 + i;
        if (tx == 0 && gr < NN) {
            g_asrc[gr * HH + head] = vs;
            g_adst[gr * HH + head] = vd;
        }
    }
}

// ---------------- edge fetch helper -------------------------------------------
__device__ __forceinline__ int edge_at(const void* edge, long long idx, int is64) {
    if (is64) return (int)((const long long*)edge)[idx];
    return ((const int*)edge)[idx];
}

// ---------------- count in-degrees: EB edges per thread (MLP) -----------------
__global__ void count_kernel(const void* __restrict__ edge) {
    int e0 = (blockIdx.x * blockDim.x + threadIdx.x) * EB;
    if (e0 >= ET) return;
    int is64 = g_is64;
    int d[EB];
#pragma unroll
    for (int q = 0; q < EB; q++) {
        int e = e0 + q;
        d[q] = -1;
        if (e < ET)
            d[q] = (e < EE) ? edge_at(edge, (long long)EE + e, is64) : (e - EE);
    }
#pragma unroll
    for (int q = 0; q < EB; q++)
        if ((unsigned)d[q] < NN) atomicAdd(&g_count[d[q]], 1);
}

// ---------------- exclusive scan of counts -> offsets (single block) ----------
__global__ void scan_kernel() {
    const int CH = 10;
    int tid = threadIdx.x;
    int base = tid * CH;
    int vals[CH];
    int tsum = 0;
#pragma unroll
    for (int c = 0; c < CH; c++) {
        int idx = base + c;
        int v = (idx < NN) ? g_count[idx] : 0;
        vals[c] = v;
        tsum += v;
    }
    int lane = tid & 31, wid = tid >> 5;
    int inc = tsum;
#pragma unroll
    for (int off = 1; off < 32; off <<= 1) {
        int y = __shfl_up_sync(0xFFFFFFFFu, inc, off);
        if (lane >= off) inc += y;
    }
    __shared__ int wsum[32];
    if (lane == 31) wsum[wid] = inc;
    __syncthreads();
    if (wid == 0) {
        int w = wsum[lane];
        int wi = w;
#pragma unroll
        for (int off = 1; off < 32; off <<= 1) {
            int y = __shfl_up_sync(0xFFFFFFFFu, wi, off);
            if (lane >= off) wi += y;
        }
        wsum[lane] = wi - w;
    }
    __syncthreads();
    int ex = (inc - tsum) + wsum[wid];
    int run = ex;
#pragma unroll
    for (int c = 0; c < CH; c++) {
        int idx = base + c;
        if (idx < NN) g_off[idx] = run;
        run += vals[c];
    }
    if (tid == 1023) g_off[NN] = run;
}

// ---------------- scatter edges into CSR: EB edges per thread -----------------
__global__ void fill_kernel(const void* __restrict__ edge) {
    int e0 = (blockIdx.x * blockDim.x + threadIdx.x) * EB;
    if (e0 >= ET) return;
    int is64 = g_is64;
    int s[EB], d[EB];
#pragma unroll
    for (int q = 0; q < EB; q++) {
        int e = e0 + q;
        s[q] = -1; d[q] = -1;
        if (e < ET) {
            if (e < EE) {
                s[q] = edge_at(edge, (long long)e, is64);
                d[q] = edge_at(edge, (long long)EE + e, is64);
            } else {
                s[q] = e - EE; d[q] = e - EE;
            }
        }
    }
#pragma unroll
    for (int q = 0; q < EB; q++) {
        if ((unsigned)d[q] >= NN || (unsigned)s[q] >= NN) continue;
        int pos = g_off[d[q]] + atomicAdd(&g_cursor[d[q]], 1);
        if ((unsigned)pos < ET) g_src[pos] = s[q];
    }
}

// ---------------- softmax + weighted aggregation (all heads in one block) -----
// 128 threads per node. Thread t owns channels [t*4, t*4+4); head = t>>5.
// Online-softmax chunking handles arbitrary degree (1 chunk when deg <= CAP).
__global__ void __launch_bounds__(128) agg_kernel(
        const float* __restrict__ bias, float* __restrict__ out) {
    const int i    = blockIdx.x;
    const int tid  = threadIdx.x;
    const int head = tid >> 5;
    const int lane = tid & 31;
    const int beg  = g_off[i];
    const int deg  = g_off[i + 1] - beg;

    __shared__ float s_e[HH * CAP];
    __shared__ int   s_src[CAP];

    const float4 adst = *(const float4*)&g_adst[i * HH];

    float m_run = -INFINITY;
    float s_run = 0.f;
    float4 acc = make_float4(0.f, 0.f, 0.f, 0.f);

    for (int c0 = 0; c0 < deg; c0 += CAP) {
        const int cl = min(CAP, deg - c0);

        for (int j = tid; j < cl; j += 128) {
            int s = g_src[beg + c0 + j];
            s_src[j] = s;
            float4 a = *(const float4*)&g_asrc[s * HH];
            float l0 = a.x + adst.x; l0 = (l0 > 0.f) ? l0 : 0.2f * l0;
            float l1 = a.y + adst.y; l1 = (l1 > 0.f) ? l1 : 0.2f * l1;
            float l2 = a.z + adst.z; l2 = (l2 > 0.f) ? l2 : 0.2f * l2;
            float l3 = a.w + adst.w; l3 = (l3 > 0.f) ? l3 : 0.2f * l3;
            s_e[0 * CAP + j] = l0;
            s_e[1 * CAP + j] = l1;
            s_e[2 * CAP + j] = l2;
            s_e[3 * CAP + j] = l3;
        }
        __syncthreads();

        float m_new = -INFINITY;
        for (int j = lane; j < cl; j += 32)
            m_new = fmaxf(m_new, s_e[head * CAP + j]);
#pragma unroll
        for (int off = 16; off > 0; off >>= 1)
            m_new = fmaxf(m_new, __shfl_xor_sync(0xFFFFFFFFu, m_new, off));

        float m2 = fmaxf(m_run, m_new);
        float scale = __expf(m_run - m2);   // exp(-inf)=0 handles first chunk

        float csum = 0.f;
        for (int j = lane; j < cl; j += 32) {
            float e = __expf(s_e[head * CAP + j] - m2);
            s_e[head * CAP + j] = e;
            csum += e;
        }
#pragma unroll
        for (int off = 16; off > 0; off >>= 1)
            csum += __shfl_xor_sync(0xFFFFFFFFu, csum, off);

        s_run = s_run * scale + csum;
        m_run = m2;
        acc.x *= scale; acc.y *= scale; acc.z *= scale; acc.w *= scale;
        __syncthreads();

        // gather: one 8-byte fp16 load per thread per edge (coalesced 1KB rows)
#pragma unroll 4
        for (int k = 0; k < cl; k++) {
            int s = s_src[k];
            float al = s_e[head * CAP + k];
            uint2 u = *(const uint2*)&g_h2[(size_t)s * (HC / 2) + tid * 2];
            float2 va = __half22float2(*(__half2*)&u.x);
            float2 vb = __half22float2(*(__half2*)&u.y);
            acc.x += al * va.x;
            acc.y += al * va.y;
            acc.z += al * vb.x;
            acc.w += al * vb.y;
        }
        __syncthreads();
    }

    const float inv = 1.f / (s_run + 1e-16f);
    const float4 b = *(const float4*)&bias[tid * 4];
    float4 o;
    o.x = acc.x * inv + b.x;
    o.y = acc.y * inv + b.y;
    o.z = acc.z * inv + b.z;
    o.w = acc.w * inv + b.w;
    *(float4*)&out[(size_t)i * HC + tid * 4] = o;
}

// ---------------- launch -------------------------------------------------------
extern "C" void kernel_launch(void* const* d_in, const int* in_sizes, int n_in,
                              void* d_out, int out_size) {
    const float* x       = (const float*)d_in[0];
    const float* W       = (const float*)d_in[1];
    const float* att_src = (const float*)d_in[2];
    const float* att_dst = (const float*)d_in[3];
    const float* bias    = (const float*)d_in[4];
    const void*  edge    = d_in[5];
    float*       out     = (float*)d_out;

    setup_kernel<<<(NN + 255) / 256, 256>>>((const int*)edge);
    gemm_kernel<<<dim3((NN + 127) / 128, HH), 256>>>(x, W, att_src, att_dst);
    count_kernel<<<(ET + 256 * EB - 1) / (256 * EB), 256>>>(edge);
    scan_kernel<<<1, 1024>>>();
    fill_kernel<<<(ET + 256 * EB - 1) / (256 * EB), 256>>>(edge);
    agg_kernel<<<NN, 128>>>(bias, out);
}

// round 7
// speedup vs baseline: 1.9121x; 1.1829x over previous
#include <cuda_runtime.h>
#include <cuda_fp16.h>
#include <math.h>

// Problem constants (fixed by the dataset)
#define NN    10000          // nodes
#define EE    320000         // edges (before self loops)
#define ET    (EE + NN)      // edges incl. self loops
#define HH    4              // heads
#define CC    128            // channels per head
#define HC    (HH * CC)      // 512
#define CAP   512            // agg chunk size (edges per shared-mem chunk)
#define EB    4              // edges per thread in count/fill

// ---------------- scratch (static device globals; no allocs allowed) ----------
__device__ __half2 g_h2[NN * HC / 2];   // projected features, fp16 [N, H*C] (10.2 MB)
__device__ float g_asrc[NN * HH];       // per-node src attention logits [N,4]
__device__ float g_adst[NN * HH];       // per-node dst attention logits [N,4]
__device__ int   g_count[NN];           // in-degree counts
__device__ int   g_off[NN + 1];         // CSR offsets
__device__ int   g_cursor[NN];          // fill cursors
__device__ int   g_src[ET];             // edge sources sorted by destination
__device__ int   g_is64;                // 1 if edge buffer is int64, 0 if int32

// ---------------- setup: zero counters + detect edge dtype --------------------
// int64 little-endian with values < 2^31 => every odd int32 word is 0.
__global__ void setup_kernel(const int* __restrict__ e32) {
    int i = blockIdx.x * blockDim.x + threadIdx.x;
    if (i < NN) { g_count[i] = 0; g_cursor[i] = 0; }
    if (blockIdx.x == 0) {
        __shared__ int bad;
        if (threadIdx.x == 0) bad = 0;
        __syncthreads();
        int any = 0;
        for (int k = threadIdx.x; k < 1024; k += blockDim.x)
            any |= (e32[2 * k + 1] != 0);
        if (any) atomicOr(&bad, 1);
        __syncthreads();
        if (threadIdx.x == 0) g_is64 = bad ? 0 : 1;
    }
}

// ---------------- GEMM + fused attention dots ---------------------------------
// h[N,512] = x[N,128] @ W[128,512].  128x128 tile, 256 threads, 8x8 microtile.
// Each block's 128 cols == one full head; h stored as fp16.
__global__ void __launch_bounds__(256) gemm_kernel(
        const float* __restrict__ x, const float* __restrict__ W,
        const float* __restrict__ att_src, const float* __restrict__ att_dst) {
    __shared__ float xs[16][128];
    __shared__ float ws[16][128];
    const int tx = threadIdx.x & 15;
    const int ty = threadIdx.x >> 4;
    const int row0 = blockIdx.x * 128;
    const int head = blockIdx.y;
    const int col0 = head * CC;

    float acc[8][8];
#pragma unroll
    for (int i = 0; i < 8; i++)
#pragma unroll
        for (int j = 0; j < 8; j++) acc[i][j] = 0.f;

    for (int kk = 0; kk < CC; kk += 16) {
        {
            int m = threadIdx.x >> 1;
            int gr = row0 + m;
#pragma unroll
            for (int q = 0; q < 2; q++) {
                int k4 = (threadIdx.x & 1) * 2 + q;
                float4 v = make_float4(0.f, 0.f, 0.f, 0.f);
                if (gr < NN) v = *(const float4*)&x[gr * CC + kk + k4 * 4];
                xs[k4 * 4 + 0][m] = v.x;
                xs[k4 * 4 + 1][m] = v.y;
                xs[k4 * 4 + 2][m] = v.z;
                xs[k4 * 4 + 3][m] = v.w;
            }
        }
        {
#pragma unroll
            for (int q = 0; q < 2; q++) {
                int t = threadIdx.x + q * 256;
                int k = t >> 5;
                int c4 = t & 31;
                float4 v = *(const float4*)&W[(kk + k) * HC + col0 + c4 * 4];
                *(float4*)&ws[k][c4 * 4] = v;
            }
        }
        __syncthreads();
#pragma unroll
        for (int k = 0; k < 16; k++) {
            float a[8], b[8];
#pragma unroll
            for (int i = 0; i < 8; i++) a[i] = xs[k][ty * 8 + i];
#pragma unroll
            for (int j = 0; j < 8; j++) b[j] = ws[k][tx * 8 + j];
#pragma unroll
            for (int i = 0; i < 8; i++)
#pragma unroll
                for (int j = 0; j < 8; j++) acc[i][j] += a[i] * b[j];
        }
        __syncthreads();
    }

    // store h as fp16 (8 floats -> 4 half2 -> one 16B write)
#pragma unroll
    for (int i = 0; i < 8; i++) {
        int gr = row0 + ty * 8 + i;
        if (gr < NN) {
            union alignas(16) { __half2 h2[4]; float4 f4; } u;
#pragma unroll
            for (int j = 0; j < 4; j++)
                u.h2[j] = __floats2half2_rn(acc[i][2 * j], acc[i][2 * j + 1]);
            *(float4*)&g_h2[(size_t)gr * (HC / 2) + (col0 + tx * 8) / 2] = u.f4;
        }
    }

    // fused attention dots (fp32 accumulators)
    float as[8], ad[8];
#pragma unroll
    for (int j = 0; j < 8; j++) {
        as[j] = att_src[head * CC + tx * 8 + j];
        ad[j] = att_dst[head * CC + tx * 8 + j];
    }
#pragma unroll
    for (int i = 0; i < 8; i++) {
        float vs = 0.f, vd = 0.f;
#pragma unroll
        for (int j = 0; j < 8; j++) { vs += acc[i][j] * as[j]; vd += acc[i][j] * ad[j]; }
#pragma unroll
        for (int off = 8; off > 0; off >>= 1) {
            vs += __shfl_down_sync(0xFFFFFFFFu, vs, off, 16);
            vd += __shfl_down_sync(0xFFFFFFFFu, vd, off, 16);
        }
        int gr = row0 + ty * 8 + i;
        if (tx == 0 && gr < NN) {
            g_asrc[gr * HH + head] = vs;
            g_adst[gr * HH + head] = vd;
        }
    }
}

// ---------------- edge fetch helper -------------------------------------------
__device__ __forceinline__ int edge_at(const void* edge, long long idx, int is64) {
    if (is64) return (int)((const long long*)edge)[idx];
    return ((const int*)edge)[idx];
}

// ---------------- count in-degrees: EB edges per thread (MLP) -----------------
__global__ void count_kernel(const void* __restrict__ edge) {
    int e0 = (blockIdx.x * blockDim.x + threadIdx.x) * EB;
    if (e0 >= ET) return;
    int is64 = g_is64;
    int d[EB];
#pragma unroll
    for (int q = 0; q < EB; q++) {
        int e = e0 + q;
        d[q] = -1;
        if (e < ET)
            d[q] = (e < EE) ? edge_at(edge, (long long)EE + e, is64) : (e - EE);
    }
#pragma unroll
    for (int q = 0; q < EB; q++)
        if ((unsigned)d[q] < NN) atomicAdd(&g_count[d[q]], 1);
}

// ---------------- exclusive scan of counts -> offsets (single block) ----------
// Coalesced smem staging in, scan in registers/smem, coalesced write out.
__global__ void __launch_bounds__(1024) scan_kernel() {
    const int CH = 10;  // 1024 * 10 >= NN
    __shared__ int sc[NN];
    int tid = threadIdx.x;

    // coalesced load of counts into shared
    for (int i = tid; i < NN; i += 1024) sc[i] = g_count[i];
    __syncthreads();

    int base = tid * CH;
    int vals[CH];
    int tsum = 0;
#pragma unroll
    for (int c = 0; c < CH; c++) {
        int idx = base + c;
        int v = (idx < NN) ? sc[idx] : 0;
        vals[c] = v;
        tsum += v;
    }
    int lane = tid & 31, wid = tid >> 5;
    int inc = tsum;
#pragma unroll
    for (int off = 1; off < 32; off <<= 1) {
        int y = __shfl_up_sync(0xFFFFFFFFu, inc, off);
        if (lane >= off) inc += y;
    }
    __shared__ int wsum[32];
    if (lane == 31) wsum[wid] = inc;
    __syncthreads();
    if (wid == 0) {
        int w = wsum[lane];
        int wi = w;
#pragma unroll
        for (int off = 1; off < 32; off <<= 1) {
            int y = __shfl_up_sync(0xFFFFFFFFu, wi, off);
            if (lane >= off) wi += y;
        }
        wsum[lane] = wi - w;
    }
    __syncthreads();
    int ex = (inc - tsum) + wsum[wid];
    int run = ex;
#pragma unroll
    for (int c = 0; c < CH; c++) {
        int idx = base + c;
        if (idx < NN) sc[idx] = run;   // own slots only; reads happened above
        run += vals[c];
    }
    __syncthreads();

    // coalesced store of offsets
    for (int i = tid; i < NN; i += 1024) g_off[i] = sc[i];
    if (tid == 1023) g_off[NN] = run;  // = ET
}

// ---------------- scatter edges into CSR: EB edges per thread -----------------
__global__ void fill_kernel(const void* __restrict__ edge) {
    int e0 = (blockIdx.x * blockDim.x + threadIdx.x) * EB;
    if (e0 >= ET) return;
    int is64 = g_is64;
    int s[EB], d[EB];
#pragma unroll
    for (int q = 0; q < EB; q++) {
        int e = e0 + q;
        s[q] = -1; d[q] = -1;
        if (e < ET) {
            if (e < EE) {
                s[q] = edge_at(edge, (long long)e, is64);
                d[q] = edge_at(edge, (long long)EE + e, is64);
            } else {
                s[q] = e - EE; d[q] = e - EE;
            }
        }
    }
#pragma unroll
    for (int q = 0; q < EB; q++) {
        if ((unsigned)d[q] >= NN || (unsigned)s[q] >= NN) continue;
        int pos = g_off[d[q]] + atomicAdd(&g_cursor[d[q]], 1);
        if ((unsigned)pos < ET) g_src[pos] = s[q];
    }
}

// ---------------- softmax + weighted aggregation (all heads in one block) -----
// 128 threads per node. Thread t owns channels [t*4, t*4+4); head = t>>5.
// Online-softmax chunking handles arbitrary degree (1 chunk when deg <= CAP).
__global__ void __launch_bounds__(128) agg_kernel(
        const float* __restrict__ bias, float* __restrict__ out) {
    const int i    = blockIdx.x;
    const int tid  = threadIdx.x;
    const int head = tid >> 5;
    const int lane = tid & 31;
    const int beg  = g_off[i];
    const int deg  = g_off[i + 1] - beg;

    __shared__ float s_e[HH * CAP];
    __shared__ int   s_src[CAP];

    const float4 adst = *(const float4*)&g_adst[i * HH];

    float m_run = -INFINITY;
    float s_run = 0.f;
    float4 acc = make_float4(0.f, 0.f, 0.f, 0.f);

    for (int c0 = 0; c0 < deg; c0 += CAP) {
        const int cl = min(CAP, deg - c0);

        for (int j = tid; j < cl; j += 128) {
            int s = g_src[beg + c0 + j];
            s_src[j] = s;
            float4 a = *(const float4*)&g_asrc[s * HH];
            float l0 = a.x + adst.x; l0 = (l0 > 0.f) ? l0 : 0.2f * l0;
            float l1 = a.y + adst.y; l1 = (l1 > 0.f) ? l1 : 0.2f * l1;
            float l2 = a.z + adst.z; l2 = (l2 > 0.f) ? l2 : 0.2f * l2;
            float l3 = a.w + adst.w; l3 = (l3 > 0.f) ? l3 : 0.2f * l3;
            s_e[0 * CAP + j] = l0;
            s_e[1 * CAP + j] = l1;
            s_e[2 * CAP + j] = l2;
            s_e[3 * CAP + j] = l3;
        }
        __syncthreads();

        float m_new = -INFINITY;
        for (int j = lane; j < cl; j += 32)
            m_new = fmaxf(m_new, s_e[head * CAP + j]);
#pragma unroll
        for (int off = 16; off > 0; off >>= 1)
            m_new = fmaxf(m_new, __shfl_xor_sync(0xFFFFFFFFu, m_new, off));

        float m2 = fmaxf(m_run, m_new);
        float scale = __expf(m_run - m2);   // exp(-inf)=0 handles first chunk

        float csum = 0.f;
        for (int j = lane; j < cl; j += 32) {
            float e = __expf(s_e[head * CAP + j] - m2);
            s_e[head * CAP + j] = e;
            csum += e;
        }
#pragma unroll
        for (int off = 16; off > 0; off >>= 1)
            csum += __shfl_xor_sync(0xFFFFFFFFu, csum, off);

        s_run = s_run * scale + csum;
        m_run = m2;
        acc.x *= scale; acc.y *= scale; acc.z *= scale; acc.w *= scale;
        __syncthreads();

        // gather: one 8-byte fp16 load per thread per edge (coalesced 1KB rows)
#pragma unroll 4
        for (int k = 0; k < cl; k++) {
            int s = s_src[k];
            float al = s_e[head * CAP + k];
            uint2 u = *(const uint2*)&g_h2[(size_t)s * (HC / 2) + tid * 2];
            float2 va = __half22float2(*(__half2*)&u.x);
            float2 vb = __half22float2(*(__half2*)&u.y);
            acc.x += al * va.x;
            acc.y += al * va.y;
            acc.z += al * vb.x;
            acc.w += al * vb.y;
        }
        __syncthreads();
    }

    const float inv = 1.f / (s_run + 1e-16f);
    const float4 b = *(const float4*)&bias[tid * 4];
    float4 o;
    o.x = acc.x * inv + b.x;
    o.y = acc.y * inv + b.y;
    o.z = acc.z * inv + b.z;
    o.w = acc.w * inv + b.w;
    *(float4*)&out[(size_t)i * HC + tid * 4] = o;
}

// ---------------- launch -------------------------------------------------------
// Two streams: GEMM (x,W only) runs concurrently with the CSR build
// (edge only); both join before agg. Streams/events are created once on the
// first (correctness) call — before graph capture — so the captured graph
// contains only kernel launches and event edges.
extern "C" void kernel_launch(void* const* d_in, const int* in_sizes, int n_in,
                              void* d_out, int out_size) {
    const float* x       = (const float*)d_in[0];
    const float* W       = (const float*)d_in[1];
    const float* att_src = (const float*)d_in[2];
    const float* att_dst = (const float*)d_in[3];
    const float* bias    = (const float*)d_in[4];
    const void*  edge    = d_in[5];
    float*       out     = (float*)d_out;

    static cudaStream_t s1 = nullptr;
    static cudaEvent_t  ev_fork = nullptr, ev_gemm = nullptr;
    if (s1 == nullptr) {
        cudaStreamCreateWithFlags(&s1, cudaStreamNonBlocking);
        cudaEventCreateWithFlags(&ev_fork, cudaEventDisableTiming);
        cudaEventCreateWithFlags(&ev_gemm, cudaEventDisableTiming);
    }

    // fork: gemm on s1 (independent of the edge pipeline)
    cudaEventRecord(ev_fork, 0);
    cudaStreamWaitEvent(s1, ev_fork, 0);
    gemm_kernel<<<dim3((NN + 127) / 128, HH), 256, 0, s1>>>(x, W, att_src, att_dst);
    cudaEventRecord(ev_gemm, s1);

    // CSR build on the main stream
    setup_kernel<<<(NN + 255) / 256, 256>>>((const int*)edge);
    count_kernel<<<(ET + 256 * EB - 1) / (256 * EB), 256>>>(edge);
    scan_kernel<<<1, 1024>>>();
    fill_kernel<<<(ET + 256 * EB - 1) / (256 * EB), 256>>>(edge);

    // join: agg needs both gemm results and the CSR
    cudaStreamWaitEvent(0, ev_gemm, 0);
    agg_kernel<<<NN, 128>>>(bias, out);
}